// round 4
// baseline (speedup 1.0000x reference)
#include <cuda_runtime.h>
#include <math.h>

// Problem constants
#define B 32
#define S 2048
#define H 1024
#define HV4 (H / 4)          // 256 float4 per row
#define R 64
#define ROWS_PER_BLK 16      // d-rows per block (8 warps x 2 rows)
#define DCHUNKS 128          // 128 * 16 = 2048 -> covers worst-case cnt
#define NUBLK 256            // u-producer blocks in K2

// Scratch (no allocations allowed -> __device__ globals)
__device__ float g_ae[B * H];            // answer_emb [B,H]
__device__ float g_u[B * H];             // u = W @ answer_emb, [B,H]
__device__ float g_d[B * S];             // per-row dot d[b,s] (touched rows)
__device__ int   g_list[B * S];          // per-batch compacted touched-row list
__device__ int   g_cnt[B];               // touched-row count per batch
__device__ int   g_nblk[B];              // active d-blocks per batch
__device__ int   g_arrive[B];            // per-batch arrival counters (K1 zeroes)
__device__ int   g_ugo;                  // u-done counter (K1 zeroes)
__device__ unsigned char g_mask[B * R];  // canonicalized rubric_mask

__device__ __forceinline__ float dot4(float4 a, float4 b) {
    return a.x * b.x + a.y * b.y + a.z * b.z + a.w * b.w;
}

// ---------------------------------------------------------------------------
// K1 (prep). Grid 288 x 256.
//   bids [0,256): answer pooling. block (b, seg): 32 float4 cols of segment
//     seg; 8 warps stride span rows (serial depth <= 4); smem reduce.
//   bids [256,288): per-batch b: canonicalize mask (bool vs int32 detect),
//     mark union of valid rubric rows, compact to g_list, set cnt/nblk,
//     zero g_arrive[b]; bid 256 zeroes g_ugo.
// ---------------------------------------------------------------------------
__global__ void k_prep(const float* __restrict__ seq,
                       const int* __restrict__ aspan,
                       const int* __restrict__ rspan,
                       const unsigned char* __restrict__ rawmask) {
    int tid = threadIdx.x, lane = tid & 31, wid = tid >> 5;

    if (blockIdx.x < 256) {
        int b = blockIdx.x >> 3, seg = blockIdx.x & 7;
        int s0 = __ldg(aspan + 2 * b), s1 = __ldg(aspan + 2 * b + 1);
        const float4* base =
            (const float4*)(seq + (size_t)b * S * H) + seg * 32 + lane;
        float4 a = make_float4(0.f, 0.f, 0.f, 0.f);
        for (int s = s0 + wid; s < s1; s += 8) {
            float4 e = __ldg(base + s * HV4);
            a.x += e.x; a.y += e.y; a.z += e.z; a.w += e.w;
        }
        __shared__ float4 part[8][32];
        part[wid][lane] = a;
        __syncthreads();
        if (tid < 32) {
            float4 acc = part[0][tid];
            #pragma unroll
            for (int w = 1; w < 8; w++) {
                float4 e = part[w][tid];
                acc.x += e.x; acc.y += e.y; acc.z += e.z; acc.w += e.w;
            }
            float inv = 1.0f / (float)(s1 - s0);
            acc.x *= inv; acc.y *= inv; acc.z *= inv; acc.w *= inv;
            ((float4*)g_ae)[b * HV4 + seg * 32 + tid] = acc;
        }
        return;
    }

    // ---- mark + compact for batch b ----
    int b = blockIdx.x - 256;

    // Encoding detection: int32-coded {0,1} has all bytes at i%4!=0 zero;
    // a 1-byte bool mask (~80% true) has nonzero bytes there w.h.p.
    __shared__ int s_any;
    if (tid == 0) s_any = 0;
    __syncthreads();
    int any = 0;
    for (int i = tid; i < B * R; i += 256)
        if (i & 3) any |= rawmask[i];
    if (any) atomicOr(&s_any, 1);
    __syncthreads();
    const int is_bool = s_any;
    const int* raw32 = (const int*)rawmask;

    __shared__ unsigned char fl[S];
    for (int i = tid; i < S / 4; i += 256) ((int*)fl)[i] = 0;
    __syncthreads();

    if (tid < R) {
        int gi = b * R + tid;
        unsigned char m = is_bool ? (rawmask[gi] != 0) : (raw32[gi] != 0);
        g_mask[gi] = m;
        if (m) {
            int r0 = __ldg(rspan + gi * 2), r1 = __ldg(rspan + gi * 2 + 1);
            for (int s = r0; s < r1; s++) fl[s] = 1;
        }
    }
    __syncthreads();

    // compact: thread t owns positions [t*8, t*8+8)
    int basep = tid * 8;
    int c = 0;
    #pragma unroll
    for (int k = 0; k < 8; k++) c += fl[basep + k];

    int v = c;
    #pragma unroll
    for (int o = 1; o < 32; o <<= 1) {
        int n = __shfl_up_sync(0xffffffffu, v, o);
        if (lane >= o) v += n;
    }
    __shared__ int wsum[8], wpref[9];
    if (lane == 31) wsum[wid] = v;
    __syncthreads();
    if (tid == 0) {
        int acc = 0;
        for (int w = 0; w < 8; w++) { wpref[w] = acc; acc += wsum[w]; }
        wpref[8] = acc;
    }
    __syncthreads();

    int rank = wpref[wid] + v - c;  // exclusive prefix
    int* list = g_list + b * S;
    #pragma unroll
    for (int k = 0; k < 8; k++)
        if (fl[basep + k]) list[rank++] = basep + k;

    if (tid == 0) {
        int cnt = wpref[8];
        g_cnt[b] = cnt;
        g_nblk[b] = (cnt + ROWS_PER_BLK - 1) / ROWS_PER_BLK;
        g_arrive[b] = 0;
        if (b == 0) g_ugo = 0;
    }
}

// ---------------------------------------------------------------------------
// K2 (fused u -> d -> scores -> softmax). Grid 256 + 32*128 x 256 threads.
//   bids [0,256): u[b,h] = sum_k W[h,k]*ae[b,k]; block does 4 h-rows for all
//     32 batches (warp = 4 batches, W read exactly once). Releases g_ugo.
//   bids >= 256: block (b, chunk) computes d for 16 union rows (2/warp) after
//     spin-waiting g_ugo==256 (dead chunks exit BEFORE spinning). The last
//     arriving block of each batch computes the 64 scores + softmax.
// Release: __syncthreads + __threadfence + atomic. Acquire: atomic read +
// __threadfence + __ldcg. Deterministic: one block per batch does the tail,
// fixed summation order.
// ---------------------------------------------------------------------------
__global__ void k_fused(const float* __restrict__ seq,
                        const float* __restrict__ W,
                        const int* __restrict__ rspan,
                        float* __restrict__ out) {
    int tid = threadIdx.x, lane = tid & 31, wid = tid >> 5;

    if (blockIdx.x < NUBLK) {
        // ---- u producer ----
        int h0 = blockIdx.x * 4;
        int bbase = wid * 4;
        const float4* a0 = (const float4*)(g_ae + (size_t)(bbase + 0) * H);
        const float4* a1 = (const float4*)(g_ae + (size_t)(bbase + 1) * H);
        const float4* a2 = (const float4*)(g_ae + (size_t)(bbase + 2) * H);
        const float4* a3 = (const float4*)(g_ae + (size_t)(bbase + 3) * H);
        for (int hh = 0; hh < 4; hh++) {
            int h = h0 + hh;
            const float4* wrow = (const float4*)(W + (size_t)h * H);
            float c0 = 0.f, c1 = 0.f, c2 = 0.f, c3 = 0.f;
            #pragma unroll
            for (int kc = 0; kc < 8; kc++) {
                int ki = kc * 32 + lane;
                float4 w4 = __ldg(wrow + ki);
                c0 += dot4(w4, __ldg(a0 + ki));
                c1 += dot4(w4, __ldg(a1 + ki));
                c2 += dot4(w4, __ldg(a2 + ki));
                c3 += dot4(w4, __ldg(a3 + ki));
            }
            #pragma unroll
            for (int off = 16; off; off >>= 1) {
                c0 += __shfl_xor_sync(0xffffffffu, c0, off);
                c1 += __shfl_xor_sync(0xffffffffu, c1, off);
                c2 += __shfl_xor_sync(0xffffffffu, c2, off);
                c3 += __shfl_xor_sync(0xffffffffu, c3, off);
            }
            if (lane == 0) {
                g_u[(size_t)(bbase + 0) * H + h] = c0;
                g_u[(size_t)(bbase + 1) * H + h] = c1;
                g_u[(size_t)(bbase + 2) * H + h] = c2;
                g_u[(size_t)(bbase + 3) * H + h] = c3;
            }
        }
        __syncthreads();
        if (tid == 0) {
            __threadfence();
            atomicAdd(&g_ugo, 1);
        }
        return;
    }

    // ---- d consumer ----
    int ib = blockIdx.x - NUBLK;
    int b = ib >> 7, chunk = ib & (DCHUNKS - 1);
    int cnt = g_cnt[b];                       // written by K1: safe
    int base = chunk * ROWS_PER_BLK;
    if (base >= cnt) return;                  // dead chunk: never spins

    if (tid == 0) {
        while (atomicAdd(&g_ugo, 0) < NUBLK) __nanosleep(64);
    }
    __syncthreads();
    __threadfence();                          // acquire

    const float4* u = (const float4*)(g_u + (size_t)b * H);
    int k0 = base + wid * 2, k1 = k0 + 1;
    bool v0 = k0 < cnt, v1 = k1 < cnt;
    int s0 = v0 ? g_list[b * S + k0] : 0;
    int s1 = v1 ? g_list[b * S + k1] : 0;
    const float4* row0 = (const float4*)(seq + ((size_t)b * S + s0) * H);
    const float4* row1 = (const float4*)(seq + ((size_t)b * S + s1) * H);
    float acc0 = 0.f, acc1 = 0.f;
    #pragma unroll
    for (int i = 0; i < 8; i++) {
        int idx4 = i * 32 + lane;
        float4 uv = __ldg(u + idx4);
        if (v0) acc0 += dot4(__ldg(row0 + idx4), uv);
        if (v1) acc1 += dot4(__ldg(row1 + idx4), uv);
    }
    #pragma unroll
    for (int off = 16; off; off >>= 1) {
        acc0 += __shfl_xor_sync(0xffffffffu, acc0, off);
        acc1 += __shfl_xor_sync(0xffffffffu, acc1, off);
    }
    if (lane == 0) {
        if (v0) g_d[b * S + s0] = acc0;
        if (v1) g_d[b * S + s1] = acc1;
    }
    __syncthreads();

    __shared__ int s_last;
    if (tid == 0) {
        __threadfence();
        int old = atomicAdd(&g_arrive[b], 1);
        s_last = (old == g_nblk[b] - 1);
    }
    __syncthreads();
    if (!s_last) return;
    __threadfence();                          // acquire for g_d

    // ---- scores: 4 threads per rubric (r = tid>>2, j = tid&3) ----
    __shared__ float sc[R];
    {
        int r = tid >> 2, j = tid & 3;
        int gi = b * R + r;
        bool m = g_mask[gi] != 0;
        float val = -INFINITY;
        float part = 0.f;
        int r0 = __ldg(rspan + gi * 2), r1 = __ldg(rspan + gi * 2 + 1);
        if (m)
            for (int s = r0 + j; s < r1; s += 4)
                part += __ldcg(g_d + b * S + s);
        part += __shfl_xor_sync(0xffffffffu, part, 1);
        part += __shfl_xor_sync(0xffffffffu, part, 2);
        if (m) val = part / (float)(r1 - r0);
        if (j == 0) sc[r] = val;
    }
    __syncthreads();

    // ---- softmax over 64 by warp 0 (2 values per lane) ----
    if (wid == 0) {
        float x0 = sc[lane], x1 = sc[lane + 32];
        float m = fmaxf(x0, x1);
        #pragma unroll
        for (int off = 16; off; off >>= 1)
            m = fmaxf(m, __shfl_xor_sync(0xffffffffu, m, off));
        float e0 = expf(x0 - m), e1 = expf(x1 - m);  // expf(-inf)=0
        float sum = e0 + e1;
        #pragma unroll
        for (int off = 16; off; off >>= 1)
            sum += __shfl_xor_sync(0xffffffffu, sum, off);
        float invs = 1.0f / sum;
        out[b * R + lane] = e0 * invs;
        out[b * R + lane + 32] = e1 * invs;
    }
}

// ---------------------------------------------------------------------------
// Launch. Inputs identified by unique element counts (robust to ordering):
//   seq: 67108864, W: 1048576, b: 1, rubric_span: 4096, answer_span: 64,
//   rubric_mask: 2048
// ---------------------------------------------------------------------------
extern "C" void kernel_launch(void* const* d_in, const int* in_sizes, int n_in,
                              void* d_out, int out_size) {
    const float* seq = nullptr;
    const float* W = nullptr;
    const int* rspan = nullptr;
    const int* aspan = nullptr;
    const unsigned char* mask = nullptr;

    for (int i = 0; i < n_in; i++) {
        switch (in_sizes[i]) {
            case B * S * H: seq   = (const float*)d_in[i]; break;
            case H * H:     W     = (const float*)d_in[i]; break;
            case B * R * 2: rspan = (const int*)d_in[i]; break;
            case B * 2:     aspan = (const int*)d_in[i]; break;
            case B * R:     mask  = (const unsigned char*)d_in[i]; break;
            default: break;  // bias (size 1): cancels in softmax
        }
    }

    float* out = (float*)d_out;

    k_prep<<<288, 256>>>(seq, aspan, rspan, mask);
    k_fused<<<NUBLK + B * DCHUNKS, 256>>>(seq, W, rspan, out);
}

// round 5
// speedup vs baseline: 1.7021x; 1.7021x over previous
#include <cuda_runtime.h>
#include <math.h>

// Problem constants
#define B 32
#define S 2048
#define H 1024
#define HV4 (H / 4)          // 256 float4 per row
#define R 64
#define GBLK 32              // K3 blocks per batch

// Scratch (no allocations allowed -> __device__ globals)
__device__ float g_ae[B * H];            // answer_emb [B,H]
__device__ float g_u[B * H];             // u = W @ answer_emb, [B,H]
__device__ float g_d[B * S];             // per-unique-row dot d[b,s]
__device__ int   g_list[B * S];          // per-batch compacted touched-row list
__device__ int   g_cnt[B];               // touched-row count per batch
__device__ int   g_arrive[B];            // per-batch arrival counters (K1 zeroes)
__device__ unsigned char g_mask[B * R];  // canonicalized rubric_mask

__device__ __forceinline__ float dot4(float4 a, float4 b) {
    return a.x * b.x + a.y * b.y + a.z * b.z + a.w * b.w;
}

// ---------------------------------------------------------------------------
// K1 (prep). Grid 288 x 256.
//   bids [0,256): answer pooling. block (b, seg): 32 float4 cols of segment
//     seg; 8 warps stride span rows (serial depth <= 4); smem reduce.
//   bids [256,288): per-batch b: canonicalize mask (bool vs int32 detect),
//     mark union of valid rubric rows, compact to g_list, set g_cnt,
//     zero g_arrive[b].
// ---------------------------------------------------------------------------
__global__ void k_prep(const float* __restrict__ seq,
                       const int* __restrict__ aspan,
                       const int* __restrict__ rspan,
                       const unsigned char* __restrict__ rawmask) {
    int tid = threadIdx.x, lane = tid & 31, wid = tid >> 5;

    if (blockIdx.x < 256) {
        int b = blockIdx.x >> 3, seg = blockIdx.x & 7;
        int s0 = __ldg(aspan + 2 * b), s1 = __ldg(aspan + 2 * b + 1);
        const float4* base =
            (const float4*)(seq + (size_t)b * S * H) + seg * 32 + lane;
        float4 a = make_float4(0.f, 0.f, 0.f, 0.f);
        for (int s = s0 + wid; s < s1; s += 8) {
            float4 e = __ldg(base + s * HV4);
            a.x += e.x; a.y += e.y; a.z += e.z; a.w += e.w;
        }
        __shared__ float4 part[8][32];
        part[wid][lane] = a;
        __syncthreads();
        if (tid < 32) {
            float4 acc = part[0][tid];
            #pragma unroll
            for (int w = 1; w < 8; w++) {
                float4 e = part[w][tid];
                acc.x += e.x; acc.y += e.y; acc.z += e.z; acc.w += e.w;
            }
            float inv = 1.0f / (float)(s1 - s0);
            acc.x *= inv; acc.y *= inv; acc.z *= inv; acc.w *= inv;
            ((float4*)g_ae)[b * HV4 + seg * 32 + tid] = acc;
        }
        return;
    }

    // ---- mark + compact for batch b ----
    int b = blockIdx.x - 256;

    // Encoding detection: int32-coded {0,1} has all bytes at i%4!=0 zero;
    // a 1-byte bool mask (~80% true) has nonzero bytes there w.h.p.
    __shared__ int s_any;
    if (tid == 0) s_any = 0;
    __syncthreads();
    int any = 0;
    for (int i = tid; i < B * R; i += 256)
        if (i & 3) any |= rawmask[i];
    if (any) atomicOr(&s_any, 1);
    __syncthreads();
    const int is_bool = s_any;
    const int* raw32 = (const int*)rawmask;

    __shared__ unsigned char fl[S];
    for (int i = tid; i < S / 4; i += 256) ((int*)fl)[i] = 0;
    __syncthreads();

    if (tid < R) {
        int gi = b * R + tid;
        unsigned char m = is_bool ? (rawmask[gi] != 0) : (raw32[gi] != 0);
        g_mask[gi] = m;
        if (m) {
            int r0 = __ldg(rspan + gi * 2), r1 = __ldg(rspan + gi * 2 + 1);
            for (int s = r0; s < r1; s++) fl[s] = 1;
        }
    }
    __syncthreads();

    // compact: thread t owns positions [t*8, t*8+8)
    int basep = tid * 8;
    int c = 0;
    #pragma unroll
    for (int k = 0; k < 8; k++) c += fl[basep + k];

    int v = c;
    #pragma unroll
    for (int o = 1; o < 32; o <<= 1) {
        int n = __shfl_up_sync(0xffffffffu, v, o);
        if (lane >= o) v += n;
    }
    __shared__ int wsum[8], wpref[9];
    if (lane == 31) wsum[wid] = v;
    __syncthreads();
    if (tid == 0) {
        int acc = 0;
        for (int w = 0; w < 8; w++) { wpref[w] = acc; acc += wsum[w]; }
        wpref[8] = acc;
    }
    __syncthreads();

    int rank = wpref[wid] + v - c;  // exclusive prefix
    int* list = g_list + b * S;
    #pragma unroll
    for (int k = 0; k < 8; k++)
        if (fl[basep + k]) list[rank++] = basep + k;

    if (tid == 0) {
        g_cnt[b] = wpref[8];
        g_arrive[b] = 0;
    }
}

// ---------------------------------------------------------------------------
// K2: u[b,h] = sum_k W[h,k] * ae[b,k]. W read exactly once from HBM.
// 256 blocks x 256 threads; warp w owns 4 batches. (Known-good from R2/R3.)
// ---------------------------------------------------------------------------
__global__ void k_u(const float* __restrict__ W) {
    int h0 = blockIdx.x * 4;
    int wrp = threadIdx.x >> 5;
    int lane = threadIdx.x & 31;
    int bbase = wrp * 4;

    const float4* a0 = (const float4*)(g_ae + (size_t)(bbase + 0) * H);
    const float4* a1 = (const float4*)(g_ae + (size_t)(bbase + 1) * H);
    const float4* a2 = (const float4*)(g_ae + (size_t)(bbase + 2) * H);
    const float4* a3 = (const float4*)(g_ae + (size_t)(bbase + 3) * H);

    for (int hh = 0; hh < 4; hh++) {
        int h = h0 + hh;
        const float4* wrow = (const float4*)(W + (size_t)h * H);
        float acc0 = 0.f, acc1 = 0.f, acc2 = 0.f, acc3 = 0.f;
        #pragma unroll
        for (int kc = 0; kc < 8; kc++) {
            int ki = kc * 32 + lane;
            float4 w4 = __ldg(wrow + ki);
            acc0 += dot4(w4, __ldg(a0 + ki));
            acc1 += dot4(w4, __ldg(a1 + ki));
            acc2 += dot4(w4, __ldg(a2 + ki));
            acc3 += dot4(w4, __ldg(a3 + ki));
        }
        #pragma unroll
        for (int off = 16; off; off >>= 1) {
            acc0 += __shfl_xor_sync(0xffffffffu, acc0, off);
            acc1 += __shfl_xor_sync(0xffffffffu, acc1, off);
            acc2 += __shfl_xor_sync(0xffffffffu, acc2, off);
            acc3 += __shfl_xor_sync(0xffffffffu, acc3, off);
        }
        if (lane == 0) {
            g_u[(size_t)(bbase + 0) * H + h] = acc0;
            g_u[(size_t)(bbase + 1) * H + h] = acc1;
            g_u[(size_t)(bbase + 2) * H + h] = acc2;
            g_u[(size_t)(bbase + 3) * H + h] = acc3;
        }
    }
}

// ---------------------------------------------------------------------------
// K3: balanced dedup d + scores + softmax. Grid 1024 x 256 (8 warps).
//   Block bid: batch b = bid & 31, group j = bid >> 5 (GBLK=32 blocks/batch,
//   none dead). Warp-task = one unique row: d[b,s] = seq[b,s,:].u[b,:]
//   (8 independent float4 loads in flight per lane; all tasks equal 4KB).
//   Tasks strided: k = j*8 + wid, step 256 -> perfect balance.
//   Every block arrives on g_arrive[b]; the last one (== GBLK) computes the
//   64 rubric scores + softmax for batch b (deterministic: one block, fixed
//   summation order). Release: __threadfence + atomicAdd; acquire: atomic
//   result + __threadfence + __ldcg.
// ---------------------------------------------------------------------------
__global__ void k_d_scores(const float* __restrict__ seq,
                           const int* __restrict__ rspan,
                           float* __restrict__ out) {
    int tid = threadIdx.x, lane = tid & 31, wid = tid >> 5;
    int b = blockIdx.x & 31;
    int j = blockIdx.x >> 5;
    int cnt = g_cnt[b];

    const float4* u = (const float4*)(g_u + (size_t)b * H);
    const int* list = g_list + b * S;
    float* drow = g_d + b * S;
    const float4* sbase = (const float4*)(seq + (size_t)b * S * H);

    for (int k = j * 8 + wid; k < cnt; k += GBLK * 8) {
        int s = list[k];
        const float4* row = sbase + s * HV4;
        float acc = 0.f;
        #pragma unroll
        for (int i = 0; i < 8; i++) {
            int idx4 = i * 32 + lane;
            acc += dot4(__ldg(row + idx4), __ldg(u + idx4));
        }
        #pragma unroll
        for (int off = 16; off; off >>= 1)
            acc += __shfl_xor_sync(0xffffffffu, acc, off);
        if (lane == 0) drow[s] = acc;
    }
    __syncthreads();

    __shared__ int s_last;
    if (tid == 0) {
        __threadfence();
        int old = atomicAdd(&g_arrive[b], 1);
        s_last = (old == GBLK - 1);
    }
    __syncthreads();
    if (!s_last) return;
    __threadfence();  // acquire side for g_d

    // ---- scores: 4 threads per rubric (r = tid>>2, jj = tid&3) ----
    __shared__ float sc[R];
    {
        int r = tid >> 2, jj = tid & 3;
        int gi = b * R + r;
        bool m = g_mask[gi] != 0;
        float val = -INFINITY;
        float part = 0.f;
        int r0 = __ldg(rspan + gi * 2), r1 = __ldg(rspan + gi * 2 + 1);
        if (m)
            for (int s = r0 + jj; s < r1; s += 4)
                part += __ldcg(drow + s);
        part += __shfl_xor_sync(0xffffffffu, part, 1);
        part += __shfl_xor_sync(0xffffffffu, part, 2);
        if (m) val = part / (float)(r1 - r0);
        if (jj == 0) sc[r] = val;
    }
    __syncthreads();

    // ---- softmax over 64 by warp 0 (2 values per lane) ----
    if (wid == 0) {
        float x0 = sc[lane], x1 = sc[lane + 32];
        float m = fmaxf(x0, x1);
        #pragma unroll
        for (int off = 16; off; off >>= 1)
            m = fmaxf(m, __shfl_xor_sync(0xffffffffu, m, off));
        float e0 = expf(x0 - m), e1 = expf(x1 - m);  // expf(-inf)=0
        float sum = e0 + e1;
        #pragma unroll
        for (int off = 16; off; off >>= 1)
            sum += __shfl_xor_sync(0xffffffffu, sum, off);
        float invs = 1.0f / sum;
        out[b * R + lane] = e0 * invs;
        out[b * R + lane + 32] = e1 * invs;
    }
}

// ---------------------------------------------------------------------------
// Launch. Inputs identified by unique element counts (robust to ordering):
//   seq: 67108864, W: 1048576, b: 1, rubric_span: 4096, answer_span: 64,
//   rubric_mask: 2048
// ---------------------------------------------------------------------------
extern "C" void kernel_launch(void* const* d_in, const int* in_sizes, int n_in,
                              void* d_out, int out_size) {
    const float* seq = nullptr;
    const float* W = nullptr;
    const int* rspan = nullptr;
    const int* aspan = nullptr;
    const unsigned char* mask = nullptr;

    for (int i = 0; i < n_in; i++) {
        switch (in_sizes[i]) {
            case B * S * H: seq   = (const float*)d_in[i]; break;
            case H * H:     W     = (const float*)d_in[i]; break;
            case B * R * 2: rspan = (const int*)d_in[i]; break;
            case B * 2:     aspan = (const int*)d_in[i]; break;
            case B * R:     mask  = (const unsigned char*)d_in[i]; break;
            default: break;  // bias (size 1): cancels in softmax
        }
    }

    float* out = (float*)d_out;

    k_prep<<<288, 256>>>(seq, aspan, rspan, mask);
    k_u<<<H / 4, 256>>>(W);
    k_d_scores<<<B * GBLK, 256>>>(seq, rspan, out);
}